// round 4
// baseline (speedup 1.0000x reference)
#include <cuda_runtime.h>
#include <math.h>
#include <stdint.h>

#define SEQ 512
#define BSZ 128
#define EMBD 128
#define HID 128
#define HG  512     // 4*H
#define TAGS 7
#define BOS 4
#define EOS 5

// ---------------- scratch (static device arrays; no allocation) ----------------
__device__ float g_xw[2][SEQ][BSZ][HG];    // input projections (both dirs)
__device__ float g_hs[2][SEQ][BSZ][HID];   // hidden states fwd/bwd
__device__ float g_fts[SEQ][BSZ][8];       // tag logits (padded to 8)

__device__ __forceinline__ float sigf(float x) { return 1.0f / (1.0f + expf(-x)); }

// packed fp32x2 FMA: d = a*b + d  (two independent IEEE fp32 FMAs, Blackwell FFMA2)
__device__ __forceinline__ void fma2(unsigned long long& d,
                                     unsigned long long a, unsigned long long b) {
    asm("fma.rn.f32x2 %0, %1, %2, %0;" : "+l"(d) : "l"(a), "l"(b));
}
__device__ __forceinline__ float2 ull2f2(unsigned long long v) {
    float2 r;
    r.x = __uint_as_float((unsigned)v);
    r.y = __uint_as_float((unsigned)(v >> 32));
    return r;
}

// ================= K1: embedding gather + input projection GEMM (FFMA2) =================
// C[row=s*128+b][col=dir*512+g] = emb[sen[row]] . W_dir[g] + bias_dir[g]
// 64x64 tile, full K=128 staged once as k-pair-packed u64 elements:
//   As2[kk][row] = pack(A[row][2kk], A[row][2kk+1])   (64 x 64 u64 = 32 KB)
//   Bs2[kk][col] = pack(W[col][2kk], W[col][2kk+1])   (32 KB)
// 256 threads, 4x4 outputs/thread, accumulators hold (even-k, odd-k) partials.
__global__ __launch_bounds__(256) void k_inproj(
    const int* __restrict__ sen, const float* __restrict__ emb,
    const float* __restrict__ Wf, const float* __restrict__ bf,
    const float* __restrict__ Wb, const float* __restrict__ bb)
{
    extern __shared__ unsigned long long sm[];
    unsigned long long* As2 = sm;           // [64][64]
    unsigned long long* Bs2 = sm + 64 * 64; // [64][64]

    const int tid = threadIdx.x;
    const int row0 = blockIdx.x * 64;
    const int col0 = blockIdx.y * 64;
    const int dir  = col0 >> 9;
    const int g0   = col0 & 511;
    const float* __restrict__ W    = dir ? Wb : Wf;
    const float* __restrict__ bias = dir ? bb : bf;

    // ---- stage: thread handles row/col (tid&63), k-floats [ (tid>>6)*32, +32 ) ----
    {
        const int rc = tid & 63;
        const int kc = tid >> 6;           // 0..3
        const int kk0 = kc * 16;           // first k-pair index

        const int tok = sen[row0 + rc];
        const ulonglong2* __restrict__ srcA =
            (const ulonglong2*)(emb + (long)tok * EMBD + kc * 32);
        const ulonglong2* __restrict__ srcB =
            (const ulonglong2*)(W + (long)(g0 + rc) * EMBD + kc * 32);
#pragma unroll
        for (int i = 0; i < 8; i++) {
            ulonglong2 va = srcA[i];
            ulonglong2 vb = srcB[i];
            As2[(kk0 + 2 * i) * 64 + rc]     = va.x;
            As2[(kk0 + 2 * i + 1) * 64 + rc] = va.y;
            Bs2[(kk0 + 2 * i) * 64 + rc]     = vb.x;
            Bs2[(kk0 + 2 * i + 1) * 64 + rc] = vb.y;
        }
    }
    __syncthreads();

    const int ty = tid >> 4, tx = tid & 15;

    unsigned long long acc[4][4];
#pragma unroll
    for (int i = 0; i < 4; i++)
#pragma unroll
        for (int j = 0; j < 4; j++) acc[i][j] = 0ull;

    const unsigned long long* __restrict__ aBase = As2 + ty * 4;
    const unsigned long long* __restrict__ bBase = Bs2 + tx * 4;

#pragma unroll 4
    for (int kk = 0; kk < 64; kk++) {
        ulonglong2 aA = *(const ulonglong2*)(aBase + kk * 64);
        ulonglong2 aB = *(const ulonglong2*)(aBase + kk * 64 + 2);
        ulonglong2 bA = *(const ulonglong2*)(bBase + kk * 64);
        ulonglong2 bB = *(const ulonglong2*)(bBase + kk * 64 + 2);
        unsigned long long av[4] = {aA.x, aA.y, aB.x, aB.y};
        unsigned long long bv[4] = {bA.x, bA.y, bB.x, bB.y};
#pragma unroll
        for (int i = 0; i < 4; i++)
#pragma unroll
            for (int j = 0; j < 4; j++) fma2(acc[i][j], av[i], bv[j]);
    }

    float4 bi = *(const float4*)&bias[g0 + tx * 4];
    const float bv4[4] = {bi.x, bi.y, bi.z, bi.w};
#pragma unroll
    for (int i = 0; i < 4; i++) {
        int R = row0 + ty * 4 + i;
        int s = R >> 7, b = R & 127;
        float o[4];
#pragma unroll
        for (int j = 0; j < 4; j++) {
            float2 p = ull2f2(acc[i][j]);
            o[j] = p.x + p.y + bv4[j];
        }
        *(float4*)&g_xw[dir][s][b][g0 + tx * 4] = make_float4(o[0], o[1], o[2], o[3]);
    }
}

// ================= K2: LSTM recurrence (FFMA2, k-pair packed) =================
// 128 blocks: dir = bid>>6, batch pair = (bid&63)*2. 512 threads = one gate row each.
// h kept per-batch contiguous so h k-pairs pack naturally; Whh k-pairs pack naturally.
__global__ __launch_bounds__(512) void k_lstm(
    const float* __restrict__ Whh_f, const float* __restrict__ Whh_b)
{
    const int bid = blockIdx.x;
    const int dir = bid >> 6;
    const int b0  = (bid & 63) * 2;
    const float* __restrict__ Whh = dir ? Whh_b : Whh_f;

    const int t = threadIdx.x;
    __shared__ __align__(16) float hs0[HID];
    __shared__ __align__(16) float hs1[HID];
    __shared__ float2 gbuf[HG];

    if (t < HID) { hs0[t] = 0.0f; hs1[t] = 0.0f; }
    float c0 = 0.0f, c1 = 0.0f;
    __syncthreads();

    const ulonglong2* __restrict__ w2 = (const ulonglong2*)(Whh + t * HID);
    const ulonglong2* h20 = (const ulonglong2*)hs0;
    const ulonglong2* h21 = (const ulonglong2*)hs1;

    for (int step = 0; step < SEQ; ++step) {
        const int s = dir ? (SEQ - 1 - step) : step;
        const float* xwp = &g_xw[dir][s][b0][0];
        float xw0 = xwp[t];
        float xw1 = xwp[HG + t];

        unsigned long long acc0 = 0ull, acc1 = 0ull;  // (even-k, odd-k) partials
#pragma unroll
        for (int i = 0; i < 32; i++) {
            ulonglong2 wv = w2[i];     // packs (w4i,w4i+1), (w4i+2,w4i+3)
            ulonglong2 h0 = h20[i];    // packs (h4i,h4i+1), (h4i+2,h4i+3) for batch0
            ulonglong2 h1 = h21[i];
            fma2(acc0, wv.x, h0.x);
            fma2(acc0, wv.y, h0.y);
            fma2(acc1, wv.x, h1.x);
            fma2(acc1, wv.y, h1.y);
        }
        float2 p0 = ull2f2(acc0);
        float2 p1 = ull2f2(acc1);
        gbuf[t] = make_float2(p0.x + p0.y + xw0, p1.x + p1.y + xw1);
        __syncthreads();

        if (t < HID) {
            float2 gi = gbuf[t];
            float2 gf = gbuf[t + 128];
            float2 gg = gbuf[t + 256];
            float2 go = gbuf[t + 384];

            c0 = sigf(gf.x) * c0 + sigf(gi.x) * tanhf(gg.x);
            c1 = sigf(gf.y) * c1 + sigf(gi.y) * tanhf(gg.y);
            float nh0 = sigf(go.x) * tanhf(c0);
            float nh1 = sigf(go.y) * tanhf(c1);

            hs0[t] = nh0;
            hs1[t] = nh1;
            float* hd = &g_hs[dir][s][b0][0];
            hd[t] = nh0;
            hd[HID + t] = nh1;
        }
        __syncthreads();
    }
}

// ================= K3: hid2tag logits =================
__global__ __launch_bounds__(256) void k_fts(
    const float* __restrict__ W_out, const float* __restrict__ b_out)
{
    __shared__ float Ws[TAGS * 256];
    __shared__ float bs[TAGS];
    const int tid = threadIdx.x;
    for (int i = tid; i < TAGS * 256; i += 256) Ws[i] = W_out[i];
    if (tid < TAGS) bs[tid] = b_out[tid];
    __syncthreads();

    const int warp = tid >> 5, lane = tid & 31;
    const int rb = blockIdx.x * 8 + warp;
    const int s = rb >> 7, b = rb & 127;

    float4 hf = ((const float4*)&g_hs[0][s][b][0])[lane];
    float4 hb = ((const float4*)&g_hs[1][s][b][0])[lane];

    float mine = 0.0f;
#pragma unroll
    for (int T = 0; T < TAGS; T++) {
        const float* w = &Ws[T * 256];
        float4 wa = *(const float4*)&w[lane * 4];
        float4 wb = *(const float4*)&w[128 + lane * 4];
        float p = hf.x * wa.x + hf.y * wa.y + hf.z * wa.z + hf.w * wa.w
                + hb.x * wb.x + hb.y * wb.y + hb.z * wb.z + hb.w * wb.w;
#pragma unroll
        for (int o = 16; o > 0; o >>= 1) p += __shfl_xor_sync(0xffffffffu, p, o);
        if (lane == T) mine = p;
    }
    if (lane < TAGS) g_fts[s][b][lane] = mine + bs[lane];
}

// ================= K4: Viterbi forward + backtrace =================
__global__ __launch_bounds__(64) void k_viterbi(
    const float* __restrict__ trans, float* __restrict__ out, int out_size)
{
    const int b = blockIdx.x;
    __shared__ float sft[SEQ][TAGS];
    __shared__ unsigned char bp[SEQ][8];
    const int tid = threadIdx.x;

    for (int i = tid; i < SEQ * TAGS; i += 64) {
        int s = i / TAGS, T = i % TAGS;
        sft[s][T] = g_fts[s][b][T];
    }
    __syncthreads();
    if (tid >= 32) return;

    const int lane = tid;
    const int j = (lane < TAGS) ? lane : (TAGS - 1);
    float tr[TAGS];
#pragma unroll
    for (int p = 0; p < TAGS; p++) tr[p] = trans[j * TAGS + p];

    float fv = (lane == BOS) ? 0.0f : -10000.0f;

    for (int s = 0; s < SEQ; s++) {
        float best = -3.4e38f;
        int bi = 0;
#pragma unroll
        for (int p = 0; p < TAGS; p++) {
            float fvp = __shfl_sync(0xffffffffu, fv, p);
            float sc = fvp + tr[p];
            if (sc > best) { best = sc; bi = p; }   // strict > : first-max argmax
        }
        if (lane < TAGS) {
            bp[s][lane] = (unsigned char)bi;
            fv = best + sft[s][lane];
        }
    }

    float term = fv + trans[EOS * TAGS + j];
    float bestv = -3.4e38f;
    int bidx = 0;
#pragma unroll
    for (int p = 0; p < TAGS; p++) {
        float tv = __shfl_sync(0xffffffffu, term, p);
        if (tv > bestv) { bestv = tv; bidx = p; }
    }

    if (lane == 0) {
        int tagbase = -1;
        bool write_score = false;
        if (out_size >= 128 + SEQ * BSZ) { write_score = true; tagbase = 128; }
        else if (out_size >= SEQ * BSZ)  { tagbase = 0; }
        else                             { write_score = true; }

        if (write_score) out[b] = bestv;
        if (tagbase >= 0) {
            int cur = bidx;
            for (int s = SEQ - 1; s >= 0; s--) {
                out[tagbase + s * BSZ + b] = (float)cur;
                cur = bp[s][cur];
            }
        }
    }
}

// ================= launcher =================
extern "C" void kernel_launch(void* const* d_in, const int* in_sizes, int n_in,
                              void* d_out, int out_size)
{
    const int*   sen   = (const int*)  d_in[0];
    const float* emb   = (const float*)d_in[1];
    const float* Wih_f = (const float*)d_in[2];
    const float* Whh_f = (const float*)d_in[3];
    const float* b_f   = (const float*)d_in[4];
    const float* Wih_b = (const float*)d_in[5];
    const float* Whh_b = (const float*)d_in[6];
    const float* b_b   = (const float*)d_in[7];
    const float* W_out = (const float*)d_in[8];
    const float* b_out = (const float*)d_in[9];
    const float* trans = (const float*)d_in[10];
    float* out = (float*)d_out;

    const int ip_smem = 64 * 64 * 8 * 2;   // 64 KB
    cudaFuncSetAttribute(k_inproj, cudaFuncAttributeMaxDynamicSharedMemorySize, ip_smem);

    dim3 g1(1024, 16);
    k_inproj<<<g1, 256, ip_smem>>>(sen, emb, Wih_f, b_f, Wih_b, b_b);
    k_lstm<<<128, 512>>>(Whh_f, Whh_b);
    k_fts<<<8192, 256>>>(W_out, b_out);
    k_viterbi<<<128, 64>>>(trans, out, out_size);
}

// round 5
// speedup vs baseline: 1.1708x; 1.1708x over previous
#include <cuda_runtime.h>
#include <math.h>
#include <stdint.h>

#define SEQ 512
#define BSZ 128
#define EMBD 128
#define HID 128
#define HG  512     // 4*H
#define TAGS 7
#define BOS 4
#define EOS 5

// ---------------- scratch (static device arrays; no allocation) ----------------
__device__ float g_xw[2][SEQ][BSZ][HG];    // input projections (both dirs)
__device__ float g_hs[2][SEQ][BSZ][HID];   // hidden states fwd/bwd
__device__ float g_fts[SEQ][BSZ][8];       // tag logits (padded to 8)
__device__ float4 g_wt[2][32][HG];         // transposed Whh: [dir][k4][row] = W[row][4k4..4k4+3]

__device__ __forceinline__ float sigf(float x) { return 1.0f / (1.0f + expf(-x)); }

// ================= K0: transpose Whh for coalesced per-step reads =================
// blockIdx.x = dir*32 + k4 ; 512 threads = rows.
__global__ __launch_bounds__(512) void k_wtrans(
    const float* __restrict__ Whh_f, const float* __restrict__ Whh_b)
{
    const int dir = blockIdx.x >> 5;
    const int k4  = blockIdx.x & 31;
    const int r   = threadIdx.x;
    const float* __restrict__ W = dir ? Whh_b : Whh_f;
    float4 v;
    v.x = W[r * HID + 4 * k4 + 0];
    v.y = W[r * HID + 4 * k4 + 1];
    v.z = W[r * HID + 4 * k4 + 2];
    v.w = W[r * HID + 4 * k4 + 3];
    g_wt[dir][k4][r] = v;
}

// ================= K1: embedding gather + input projection GEMM (R2-proven) =================
__global__ __launch_bounds__(256) void k_inproj(
    const int* __restrict__ sen, const float* __restrict__ emb,
    const float* __restrict__ Wf, const float* __restrict__ bf,
    const float* __restrict__ Wb, const float* __restrict__ bb)
{
    __shared__ float As[32][64];   // k-major A tile
    __shared__ float Bs[32][64];   // k-major B tile
    __shared__ int   tok[64];

    const int tid = threadIdx.x;
    const int row0 = blockIdx.x * 64;
    const int col0 = blockIdx.y * 64;           // global col in [0,1024)
    const int dir  = col0 >> 9;
    const int g0   = col0 & 511;
    const float* __restrict__ W    = dir ? Wb : Wf;
    const float* __restrict__ bias = dir ? bb : bf;

    if (tid < 64) tok[tid] = sen[row0 + tid];
    __syncthreads();

    float acc[4][4];
#pragma unroll
    for (int i = 0; i < 4; i++)
#pragma unroll
        for (int j = 0; j < 4; j++) acc[i][j] = 0.0f;

    const int ty = tid >> 4, tx = tid & 15;
    const int lr = tid >> 2;              // 0..63
    const int kp = (tid & 3) * 8;         // 0,8,16,24

    for (int kc = 0; kc < 128; kc += 32) {
        {
            const float* src = emb + (long)tok[lr] * EMBD + kc + kp;
            float4 v0 = *(const float4*)(src);
            float4 v1 = *(const float4*)(src + 4);
            As[kp + 0][lr] = v0.x; As[kp + 1][lr] = v0.y;
            As[kp + 2][lr] = v0.z; As[kp + 3][lr] = v0.w;
            As[kp + 4][lr] = v1.x; As[kp + 5][lr] = v1.y;
            As[kp + 6][lr] = v1.z; As[kp + 7][lr] = v1.w;
        }
        {
            const float* src = W + (long)(g0 + lr) * EMBD + kc + kp;
            float4 v0 = *(const float4*)(src);
            float4 v1 = *(const float4*)(src + 4);
            Bs[kp + 0][lr] = v0.x; Bs[kp + 1][lr] = v0.y;
            Bs[kp + 2][lr] = v0.z; Bs[kp + 3][lr] = v0.w;
            Bs[kp + 4][lr] = v1.x; Bs[kp + 5][lr] = v1.y;
            Bs[kp + 6][lr] = v1.z; Bs[kp + 7][lr] = v1.w;
        }
        __syncthreads();
#pragma unroll
        for (int k = 0; k < 32; k++) {
            float4 a = *(const float4*)&As[k][ty * 4];
            float4 b = *(const float4*)&Bs[k][tx * 4];
            float av[4] = {a.x, a.y, a.z, a.w};
            float bv[4] = {b.x, b.y, b.z, b.w};
#pragma unroll
            for (int i = 0; i < 4; i++)
#pragma unroll
                for (int j = 0; j < 4; j++) acc[i][j] += av[i] * bv[j];
        }
        __syncthreads();
    }

    float4 bi = *(const float4*)&bias[g0 + tx * 4];
#pragma unroll
    for (int i = 0; i < 4; i++) {
        int R = row0 + ty * 4 + i;
        int s = R >> 7, b = R & 127;
        float4 o;
        o.x = acc[i][0] + bi.x;
        o.y = acc[i][1] + bi.y;
        o.z = acc[i][2] + bi.z;
        o.w = acc[i][3] + bi.w;
        *(float4*)&g_xw[dir][s][b][g0 + tx * 4] = o;
    }
}

// ================= K2: LSTM recurrence — coalesced transposed weight reads =================
// 128 blocks: dir = bid>>6, batch pair = (bid&63)*2. 512 threads = one gate row each.
// Weight read per step: wt[k4][r] — warp lanes (consecutive r) hit consecutive 16B
// chunks -> 4 lines per LDG.128 warp-inst instead of 32.
__global__ __launch_bounds__(512) void k_lstm()
{
    const int bid = blockIdx.x;
    const int dir = bid >> 6;
    const int b0  = (bid & 63) * 2;
    const float4* __restrict__ wt = &g_wt[dir][0][0];   // [k4*512 + r]

    const int t = threadIdx.x;
    __shared__ float2 hsm[HID];     // h for both batch elems
    __shared__ float2 gbuf[HG];     // raw gate preactivations

    if (t < HID) hsm[t] = make_float2(0.0f, 0.0f);
    float c0 = 0.0f, c1 = 0.0f;
    __syncthreads();

    const float4* h4 = (const float4*)hsm;

    for (int step = 0; step < SEQ; ++step) {
        const int s = dir ? (SEQ - 1 - step) : step;
        const float* xwp = &g_xw[dir][s][b0][0];
        float xw0 = xwp[t];
        float xw1 = xwp[HG + t];

        float a0 = 0.0f, a1 = 0.0f;
#pragma unroll
        for (int k = 0; k < 32; k++) {
            float4 w = wt[k * HG + t];     // coalesced across the warp
            float4 p = h4[2 * k];          // (h0[4k],h1[4k],h0[4k+1],h1[4k+1])
            float4 q = h4[2 * k + 1];      // (h0[4k+2],h1[4k+2],h0[4k+3],h1[4k+3])
            a0 += w.x * p.x; a1 += w.x * p.y;
            a0 += w.y * p.z; a1 += w.y * p.w;
            a0 += w.z * q.x; a1 += w.z * q.y;
            a0 += w.w * q.z; a1 += w.w * q.w;
        }
        gbuf[t] = make_float2(a0 + xw0, a1 + xw1);
        __syncthreads();

        if (t < HID) {
            float2 gi = gbuf[t];
            float2 gf = gbuf[t + 128];
            float2 gg = gbuf[t + 256];
            float2 go = gbuf[t + 384];

            c0 = sigf(gf.x) * c0 + sigf(gi.x) * tanhf(gg.x);
            c1 = sigf(gf.y) * c1 + sigf(gi.y) * tanhf(gg.y);
            float nh0 = sigf(go.x) * tanhf(c0);
            float nh1 = sigf(go.y) * tanhf(c1);

            hsm[t] = make_float2(nh0, nh1);
            float* hd = &g_hs[dir][s][b0][0];
            hd[t] = nh0;
            hd[HID + t] = nh1;
        }
        __syncthreads();
    }
}

// ================= K3: hid2tag logits =================
__global__ __launch_bounds__(256) void k_fts(
    const float* __restrict__ W_out, const float* __restrict__ b_out)
{
    __shared__ float Ws[TAGS * 256];
    __shared__ float bs[TAGS];
    const int tid = threadIdx.x;
    for (int i = tid; i < TAGS * 256; i += 256) Ws[i] = W_out[i];
    if (tid < TAGS) bs[tid] = b_out[tid];
    __syncthreads();

    const int warp = tid >> 5, lane = tid & 31;
    const int rb = blockIdx.x * 8 + warp;
    const int s = rb >> 7, b = rb & 127;

    float4 hf = ((const float4*)&g_hs[0][s][b][0])[lane];
    float4 hb = ((const float4*)&g_hs[1][s][b][0])[lane];

    float mine = 0.0f;
#pragma unroll
    for (int T = 0; T < TAGS; T++) {
        const float* w = &Ws[T * 256];
        float4 wa = *(const float4*)&w[lane * 4];
        float4 wb = *(const float4*)&w[128 + lane * 4];
        float p = hf.x * wa.x + hf.y * wa.y + hf.z * wa.z + hf.w * wa.w
                + hb.x * wb.x + hb.y * wb.y + hb.z * wb.z + hb.w * wb.w;
#pragma unroll
        for (int o = 16; o > 0; o >>= 1) p += __shfl_xor_sync(0xffffffffu, p, o);
        if (lane == T) mine = p;
    }
    if (lane < TAGS) g_fts[s][b][lane] = mine + bs[lane];
}

// ================= K4: Viterbi forward + backtrace =================
__global__ __launch_bounds__(64) void k_viterbi(
    const float* __restrict__ trans, float* __restrict__ out, int out_size)
{
    const int b = blockIdx.x;
    __shared__ float sft[SEQ][TAGS];
    __shared__ unsigned char bp[SEQ][8];
    const int tid = threadIdx.x;

    for (int i = tid; i < SEQ * TAGS; i += 64) {
        int s = i / TAGS, T = i % TAGS;
        sft[s][T] = g_fts[s][b][T];
    }
    __syncthreads();
    if (tid >= 32) return;

    const int lane = tid;
    const int j = (lane < TAGS) ? lane : (TAGS - 1);
    float tr[TAGS];
#pragma unroll
    for (int p = 0; p < TAGS; p++) tr[p] = trans[j * TAGS + p];

    float fv = (lane == BOS) ? 0.0f : -10000.0f;

    for (int s = 0; s < SEQ; s++) {
        float best = -3.4e38f;
        int bi = 0;
#pragma unroll
        for (int p = 0; p < TAGS; p++) {
            float fvp = __shfl_sync(0xffffffffu, fv, p);
            float sc = fvp + tr[p];
            if (sc > best) { best = sc; bi = p; }   // strict > : first-max argmax
        }
        if (lane < TAGS) {
            bp[s][lane] = (unsigned char)bi;
            fv = best + sft[s][lane];
        }
    }

    float term = fv + trans[EOS * TAGS + j];
    float bestv = -3.4e38f;
    int bidx = 0;
#pragma unroll
    for (int p = 0; p < TAGS; p++) {
        float tv = __shfl_sync(0xffffffffu, term, p);
        if (tv > bestv) { bestv = tv; bidx = p; }
    }

    if (lane == 0) {
        int tagbase = -1;
        bool write_score = false;
        if (out_size >= 128 + SEQ * BSZ) { write_score = true; tagbase = 128; }
        else if (out_size >= SEQ * BSZ)  { tagbase = 0; }
        else                             { write_score = true; }

        if (write_score) out[b] = bestv;
        if (tagbase >= 0) {
            int cur = bidx;
            for (int s = SEQ - 1; s >= 0; s--) {
                out[tagbase + s * BSZ + b] = (float)cur;
                cur = bp[s][cur];
            }
        }
    }
}

// ================= launcher =================
extern "C" void kernel_launch(void* const* d_in, const int* in_sizes, int n_in,
                              void* d_out, int out_size)
{
    const int*   sen   = (const int*)  d_in[0];
    const float* emb   = (const float*)d_in[1];
    const float* Wih_f = (const float*)d_in[2];
    const float* Whh_f = (const float*)d_in[3];
    const float* b_f   = (const float*)d_in[4];
    const float* Wih_b = (const float*)d_in[5];
    const float* Whh_b = (const float*)d_in[6];
    const float* b_b   = (const float*)d_in[7];
    const float* W_out = (const float*)d_in[8];
    const float* b_out = (const float*)d_in[9];
    const float* trans = (const float*)d_in[10];
    float* out = (float*)d_out;

    k_wtrans<<<64, 512>>>(Whh_f, Whh_b);
    dim3 g1(1024, 16);
    k_inproj<<<g1, 256>>>(sen, emb, Wih_f, b_f, Wih_b, b_b);
    k_lstm<<<128, 512>>>();
    k_fts<<<8192, 256>>>(W_out, b_out);
    k_viterbi<<<128, 64>>>(trans, out, out_size);
}

// round 6
// speedup vs baseline: 1.3136x; 1.1219x over previous
#include <cuda_runtime.h>
#include <math.h>
#include <stdint.h>

#define SEQ 512
#define BSZ 128
#define EMBD 128
#define HID 128
#define HG  512     // 4*H
#define TAGS 7
#define BOS 4
#define EOS 5

// ---------------- scratch (static device arrays; no allocation) ----------------
__device__ float g_xw[2][SEQ][BSZ][HG];    // input projections (both dirs)
__device__ float g_hs[2][SEQ][BSZ][HID];   // hidden states fwd/bwd
__device__ float g_fts[SEQ][BSZ][8];       // tag logits (padded to 8)

__device__ __forceinline__ float sigf(float x) { return 1.0f / (1.0f + expf(-x)); }

// ================= K1: embedding gather + input projection GEMM (R2-proven) =================
__global__ __launch_bounds__(256) void k_inproj(
    const int* __restrict__ sen, const float* __restrict__ emb,
    const float* __restrict__ Wf, const float* __restrict__ bf,
    const float* __restrict__ Wb, const float* __restrict__ bb)
{
    __shared__ float As[32][64];   // k-major A tile
    __shared__ float Bs[32][64];   // k-major B tile
    __shared__ int   tok[64];

    const int tid = threadIdx.x;
    const int row0 = blockIdx.x * 64;
    const int col0 = blockIdx.y * 64;           // global col in [0,1024)
    const int dir  = col0 >> 9;
    const int g0   = col0 & 511;
    const float* __restrict__ W    = dir ? Wb : Wf;
    const float* __restrict__ bias = dir ? bb : bf;

    if (tid < 64) tok[tid] = sen[row0 + tid];
    __syncthreads();

    float acc[4][4];
#pragma unroll
    for (int i = 0; i < 4; i++)
#pragma unroll
        for (int j = 0; j < 4; j++) acc[i][j] = 0.0f;

    const int ty = tid >> 4, tx = tid & 15;
    const int lr = tid >> 2;              // 0..63
    const int kp = (tid & 3) * 8;         // 0,8,16,24

    for (int kc = 0; kc < 128; kc += 32) {
        {
            const float* src = emb + (long)tok[lr] * EMBD + kc + kp;
            float4 v0 = *(const float4*)(src);
            float4 v1 = *(const float4*)(src + 4);
            As[kp + 0][lr] = v0.x; As[kp + 1][lr] = v0.y;
            As[kp + 2][lr] = v0.z; As[kp + 3][lr] = v0.w;
            As[kp + 4][lr] = v1.x; As[kp + 5][lr] = v1.y;
            As[kp + 6][lr] = v1.z; As[kp + 7][lr] = v1.w;
        }
        {
            const float* src = W + (long)(g0 + lr) * EMBD + kc + kp;
            float4 v0 = *(const float4*)(src);
            float4 v1 = *(const float4*)(src + 4);
            Bs[kp + 0][lr] = v0.x; Bs[kp + 1][lr] = v0.y;
            Bs[kp + 2][lr] = v0.z; Bs[kp + 3][lr] = v0.w;
            Bs[kp + 4][lr] = v1.x; Bs[kp + 5][lr] = v1.y;
            Bs[kp + 6][lr] = v1.z; Bs[kp + 7][lr] = v1.w;
        }
        __syncthreads();
#pragma unroll
        for (int k = 0; k < 32; k++) {
            float4 a = *(const float4*)&As[k][ty * 4];
            float4 b = *(const float4*)&Bs[k][tx * 4];
            float av[4] = {a.x, a.y, a.z, a.w};
            float bv[4] = {b.x, b.y, b.z, b.w};
#pragma unroll
            for (int i = 0; i < 4; i++)
#pragma unroll
                for (int j = 0; j < 4; j++) acc[i][j] += av[i] * bv[j];
        }
        __syncthreads();
    }

    float4 bi = *(const float4*)&bias[g0 + tx * 4];
#pragma unroll
    for (int i = 0; i < 4; i++) {
        int R = row0 + ty * 4 + i;
        int s = R >> 7, b = R & 127;
        float4 o;
        o.x = acc[i][0] + bi.x;
        o.y = acc[i][1] + bi.y;
        o.z = acc[i][2] + bi.z;
        o.w = acc[i][3] + bi.w;
        *(float4*)&g_xw[dir][s][b][g0 + tx * 4] = o;
    }
}

// ================= K2: LSTM recurrence (R2 dot phase + prefetch/streaming/pointwise-split) =================
// 128 blocks: dir = bid>>6, batch pair = (bid&63)*2. 512 threads = one gate row each.
__global__ __launch_bounds__(512) void k_lstm(
    const float* __restrict__ Whh_f, const float* __restrict__ Whh_b)
{
    const int bid = blockIdx.x;
    const int dir = bid >> 6;
    const int b0  = (bid & 63) * 2;
    const float* __restrict__ Whh = dir ? Whh_b : Whh_f;

    const int t = threadIdx.x;
    __shared__ float2 hsm[HID];     // h for both batch elems (interleaved b0,b1)
    __shared__ float2 gbuf[HG];     // raw gate preactivations

    if (t < HID) hsm[t] = make_float2(0.0f, 0.0f);
    float c = 0.0f;                 // cell state: thread t<256 owns (b=t>>7, hid=t&127)
    __syncthreads();

    const float4* __restrict__ w4 = (const float4*)(Whh + t * HID);
    const float4* h4 = (const float4*)hsm;

    // prefetch xw for step 0 (streaming: read-once, don't pollute L1 weight set)
    {
        const int s0 = dir ? (SEQ - 1) : 0;
        const float* xwp = &g_xw[dir][s0][b0][0];
        // fallthrough into loop with these
        float xw0 = __ldcs(xwp + t);
        float xw1 = __ldcs(xwp + HG + t);

        for (int step = 0; step < SEQ; ++step) {
            const int s = dir ? (SEQ - 1 - step) : step;

            float a0 = 0.0f, a1 = 0.0f;
#pragma unroll
            for (int k = 0; k < 32; k++) {
                float4 w = w4[k];
                float4 p = h4[2 * k];
                float4 q = h4[2 * k + 1];
                a0 += w.x * p.x; a1 += w.x * p.y;
                a0 += w.y * p.z; a1 += w.y * p.w;
                a0 += w.z * q.x; a1 += w.z * q.y;
                a0 += w.w * q.z; a1 += w.w * q.w;
            }
            gbuf[t] = make_float2(a0 + xw0, a1 + xw1);

            // prefetch next step's xw NOW — completes under barrier+pointwise
            if (step + 1 < SEQ) {
                const int sn = dir ? (SEQ - 2 - step) : (step + 1);
                const float* xwn = &g_xw[dir][sn][b0][0];
                xw0 = __ldcs(xwn + t);
                xw1 = __ldcs(xwn + HG + t);
            }
            __syncthreads();

            if (t < 256) {
                const int b   = t >> 7;       // 0 or 1
                const int hid = t & 127;
                // pick this batch's component from the interleaved gate buffer
                float gi = b ? gbuf[hid].y        : gbuf[hid].x;
                float gf = b ? gbuf[hid + 128].y  : gbuf[hid + 128].x;
                float gg = b ? gbuf[hid + 256].y  : gbuf[hid + 256].x;
                float go = b ? gbuf[hid + 384].y  : gbuf[hid + 384].x;

                c = sigf(gf) * c + sigf(gi) * tanhf(gg);
                float nh = sigf(go) * tanhf(c);

                ((float*)hsm)[hid * 2 + b] = nh;                       // h for next dot
                __stcs(&g_hs[dir][s][b0][b * HID + hid], nh);          // write-once stream
            }
            __syncthreads();
        }
    }
}

// ================= K3: hid2tag logits =================
__global__ __launch_bounds__(256) void k_fts(
    const float* __restrict__ W_out, const float* __restrict__ b_out)
{
    __shared__ float Ws[TAGS * 256];
    __shared__ float bs[TAGS];
    const int tid = threadIdx.x;
    for (int i = tid; i < TAGS * 256; i += 256) Ws[i] = W_out[i];
    if (tid < TAGS) bs[tid] = b_out[tid];
    __syncthreads();

    const int warp = tid >> 5, lane = tid & 31;
    const int rb = blockIdx.x * 8 + warp;
    const int s = rb >> 7, b = rb & 127;

    float4 hf = ((const float4*)&g_hs[0][s][b][0])[lane];
    float4 hb = ((const float4*)&g_hs[1][s][b][0])[lane];

    float mine = 0.0f;
#pragma unroll
    for (int T = 0; T < TAGS; T++) {
        const float* w = &Ws[T * 256];
        float4 wa = *(const float4*)&w[lane * 4];
        float4 wb = *(const float4*)&w[128 + lane * 4];
        float p = hf.x * wa.x + hf.y * wa.y + hf.z * wa.z + hf.w * wa.w
                + hb.x * wb.x + hb.y * wb.y + hb.z * wb.z + hb.w * wb.w;
#pragma unroll
        for (int o = 16; o > 0; o >>= 1) p += __shfl_xor_sync(0xffffffffu, p, o);
        if (lane == T) mine = p;
    }
    if (lane < TAGS) g_fts[s][b][lane] = mine + bs[lane];
}

// ================= K4: Viterbi forward + backtrace =================
__global__ __launch_bounds__(64) void k_viterbi(
    const float* __restrict__ trans, float* __restrict__ out, int out_size)
{
    const int b = blockIdx.x;
    __shared__ float sft[SEQ][TAGS];
    __shared__ unsigned char bp[SEQ][8];
    const int tid = threadIdx.x;

    for (int i = tid; i < SEQ * TAGS; i += 64) {
        int s = i / TAGS, T = i % TAGS;
        sft[s][T] = g_fts[s][b][T];
    }
    __syncthreads();
    if (tid >= 32) return;

    const int lane = tid;
    const int j = (lane < TAGS) ? lane : (TAGS - 1);
    float tr[TAGS];
#pragma unroll
    for (int p = 0; p < TAGS; p++) tr[p] = trans[j * TAGS + p];

    float fv = (lane == BOS) ? 0.0f : -10000.0f;

    for (int s = 0; s < SEQ; s++) {
        float best = -3.4e38f;
        int bi = 0;
#pragma unroll
        for (int p = 0; p < TAGS; p++) {
            float fvp = __shfl_sync(0xffffffffu, fv, p);
            float sc = fvp + tr[p];
            if (sc > best) { best = sc; bi = p; }   // strict > : first-max argmax
        }
        if (lane < TAGS) {
            bp[s][lane] = (unsigned char)bi;
            fv = best + sft[s][lane];
        }
    }

    float term = fv + trans[EOS * TAGS + j];
    float bestv = -3.4e38f;
    int bidx = 0;
#pragma unroll
    for (int p = 0; p < TAGS; p++) {
        float tv = __shfl_sync(0xffffffffu, term, p);
        if (tv > bestv) { bestv = tv; bidx = p; }
    }

    if (lane == 0) {
        int tagbase = -1;
        bool write_score = false;
        if (out_size >= 128 + SEQ * BSZ) { write_score = true; tagbase = 128; }
        else if (out_size >= SEQ * BSZ)  { tagbase = 0; }
        else                             { write_score = true; }

        if (write_score) out[b] = bestv;
        if (tagbase >= 0) {
            int cur = bidx;
            for (int s = SEQ - 1; s >= 0; s--) {
                out[tagbase + s * BSZ + b] = (float)cur;
                cur = bp[s][cur];
            }
        }
    }
}

// ================= launcher =================
extern "C" void kernel_launch(void* const* d_in, const int* in_sizes, int n_in,
                              void* d_out, int out_size)
{
    const int*   sen   = (const int*)  d_in[0];
    const float* emb   = (const float*)d_in[1];
    const float* Wih_f = (const float*)d_in[2];
    const float* Whh_f = (const float*)d_in[3];
    const float* b_f   = (const float*)d_in[4];
    const float* Wih_b = (const float*)d_in[5];
    const float* Whh_b = (const float*)d_in[6];
    const float* b_b   = (const float*)d_in[7];
    const float* W_out = (const float*)d_in[8];
    const float* b_out = (const float*)d_in[9];
    const float* trans = (const float*)d_in[10];
    float* out = (float*)d_out;

    dim3 g1(1024, 16);
    k_inproj<<<g1, 256>>>(sen, emb, Wih_f, b_f, Wih_b, b_b);
    k_lstm<<<128, 512>>>(Whh_f, Whh_b);
    k_fts<<<8192, 256>>>(W_out, b_out);
    k_viterbi<<<128, 64>>>(trans, out, out_size);
}